// round 12
// baseline (speedup 1.0000x reference)
#include <cuda_runtime.h>
#include <math.h>
#include <stdint.h>

// Problem constants (fixed by the dataset)
#define NMAX 25000
#define PMAX 400000

// ---------------- scratch (static device globals; no allocs) ----------------
__device__ float  g_hedge[(size_t)PMAX * 32];   // per-edge edge features [P,32]
__device__ float4 g_att[PMAX];                  // att (then exp(att-max)) [P,4]
__device__ float4 g_dird[PMAX];                 // dir.x,dir.y,dir.z,d
__device__ float4 g_hisem[(size_t)NMAX * 32];   // h_i_sem [N,128] as float4
__device__ float  g_comb[(size_t)NMAX * 96];    // comb_sum [N][3][32]
__device__ float4 g_smax[NMAX];                 // segment max of att [N,4]
__device__ float4 g_ssum[NMAX];                 // segment sum of exp [N,4]
__device__ float  g_cnt[NMAX];                  // edges per receiver

// ---------------- math helpers ----------------
__device__ __forceinline__ float siluf(float x) { return x / (1.f + expf(-x)); }
__device__ __forceinline__ float celu2f(float x) { return x > 0.f ? x : 2.f * expm1f(0.5f * x); }

__device__ __forceinline__ void atomicMaxF(float* addr, float val) {
    int* ia = (int*)addr;
    int old = *ia;
    while (__int_as_float(old) < val) {
        int assumed = old;
        old = atomicCAS(ia, assumed, __float_as_int(val));
        if (old == assumed) break;
    }
}

__device__ __forceinline__ void redAddV4(float* addr, float4 v) {
    asm volatile("red.global.add.v4.f32 [%0], {%1,%2,%3,%4};"
                 :: "l"(addr), "f"(v.x), "f"(v.y), "f"(v.z), "f"(v.w) : "memory");
}

// PhysNet RBF constants
constexpr double E0d = 0.6065306597126334;
constexpr float  E0c = (float)E0d;
constexpr float  MUSTEP = (float)((1.0 - E0d) / 49.0);
constexpr float  BETAc = (float)(1.0 / ((0.04 * (1.0 - E0d)) * (0.04 * (1.0 - E0d))));

// ---------------- kernel 0: init accumulators ----------------
__global__ void kInit(int N) {
    int t = blockIdx.x * blockDim.x + threadIdx.x;
    if (t < N * 128) ((float*)g_hisem)[t] = 0.f;
    if (t < N * 96)  g_comb[t] = 0.f;
    if (t < N * 4) {
        ((float*)g_smax)[t] = __int_as_float(0xff800000); // -inf
        ((float*)g_ssum)[t] = 0.f;
    }
    if (t < N) g_cnt[t] = 0.f;
}

// ---------------- kernel A: per-edge MLPs as tiled GEMMs ----------------
// Tile = 128 edges, 512 threads/block, persistent over tiles.
// smem layout (floats):
#define LDA 132
#define OFF_WEIN  0                     // [128][64]  = 8192
#define OFF_WEO1  8192                  // [192][64]  = 12288
#define OFF_WEO2  20480                 // [64][32]   = 2048
#define OFF_WATT  22528                 // [32][4]    = 128
#define OFF_BEIN  22656                 // 64
#define OFF_BEO1  22720                 // 64
#define OFF_BEO2  22784                 // 32
#define OFF_BATT  22816                 // 16 (4 used)
#define OFF_SD    22832                 // 128
#define OFF_SED   22960                 // 128
#define OFF_SI    23088                 // 128 (ints)
#define OFF_A2T   23216                 // [192][132] = 25344
#define SMA_FLOATS (23216 + 192 * LDA)  // 48560 floats = 194240 B

__global__ void __launch_bounds__(512, 1)
kA(const float* __restrict__ h, const float* __restrict__ x,
   const int* __restrict__ idx_i, const int* __restrict__ idx_j,
   const float* __restrict__ W_ein, const float* __restrict__ b_ein,
   const float* __restrict__ W_eo1, const float* __restrict__ b_eo1,
   const float* __restrict__ W_eo2, const float* __restrict__ b_eo2,
   const float* __restrict__ W_att, const float* __restrict__ b_att,
   int P)
{
    extern __shared__ float sm[];
    float* sWein = sm + OFF_WEIN;
    float* sWeo1 = sm + OFF_WEO1;
    float* sWeo2 = sm + OFF_WEO2;
    float* sWatt = sm + OFF_WATT;
    float* sbein = sm + OFF_BEIN;
    float* sbeo1 = sm + OFF_BEO1;
    float* sbeo2 = sm + OFF_BEO2;
    float* sbatt = sm + OFF_BATT;
    float* sd    = sm + OFF_SD;
    float* sed   = sm + OFF_SED;
    int*   si    = (int*)(sm + OFF_SI);
    float* A2t   = sm + OFF_A2T;

    const int tid = threadIdx.x;

    // load weights once per block
    for (int t = tid; t < 8192; t += 512) {
        int m = t >> 6, k = t & 63;
        sWein[t] = (k < 50) ? W_ein[m * 50 + k] : 0.f;
    }
    for (int t = tid; t < 12288; t += 512) {
        int m = t >> 6;
        sWeo1[t] = (m < 179) ? W_eo1[t] : 0.f;
    }
    for (int t = tid; t < 2048; t += 512) sWeo2[t] = W_eo2[t];
    if (tid < 128) sWatt[tid] = W_att[tid];
    if (tid < 64)  sbein[tid] = (tid < 50) ? b_ein[tid] : 0.f;
    if (tid < 64)  sbeo1[tid] = b_eo1[tid];
    if (tid < 32)  sbeo2[tid] = b_eo2[tid];
    if (tid < 4)   sbatt[tid] = b_att[tid];

    const int numTiles = (P + 127) >> 7;
    const int r  = tid & 31;   // edge group (4 edges) for GEMM1/2
    const int cg = tid >> 5;   // out group (4 outs)
    const int r2 = tid & 15;   // edge group (8 edges) for GEMM3
    const int c2 = tid >> 4;   // out (1 of 32)
    const int ea = tid >> 2;   // edge for att phase
    const int hh = tid & 3;    // head for att phase

    for (int tile = blockIdx.x; tile < numTiles; tile += gridDim.x) {
        const int p0 = tile << 7;
        __syncthreads();   // previous tile fully consumed

        // ---- gather: build A2t rows 0..127 (h_cat transposed), geometry ----
        {
            int e = tid >> 2, q = tid & 3;
            int p = p0 + e;
            int i = 0, j = 0;
            bool valid = (p < P);
            if (valid) { i = idx_i[p]; j = idx_j[p]; }
            if (q == 0) {
                if (valid) {
                    si[e] = i;
                    float rx = x[3 * j]     - x[3 * i];
                    float ry = x[3 * j + 1] - x[3 * i + 1];
                    float rz = x[3 * j + 2] - x[3 * i + 2];
                    float d = sqrtf(rx * rx + ry * ry + rz * rz + 1e-8f);
                    float invd = 1.f / (d + 1e-8f);
                    g_dird[p] = make_float4(rx * invd, ry * invd, rz * invd, d);
                    sd[e] = d;
                    sed[e] = expf(-d);
                } else {
                    si[e] = 0; sd[e] = 0.f; sed[e] = 1.f;
                }
            }
            const float* hi = h + (size_t)i * 64 + q * 16;
            const float* hj = h + (size_t)j * 64 + q * 16;
            #pragma unroll
            for (int kk = 0; kk < 16; kk++) {
                float v0 = valid ? hi[kk] : 0.f;
                float v1 = valid ? hj[kk] : 0.f;
                A2t[(q * 16 + kk) * LDA + e]      = v0;
                A2t[(64 + q * 16 + kk) * LDA + e] = v1;
            }
        }
        __syncthreads();

        // ---- GEMM1: [128e,128] @ W_ein[128,64] -> filtered rows 128..191 ----
        {
            float acc[4][4];
            #pragma unroll
            for (int a = 0; a < 4; a++)
                #pragma unroll
                for (int b = 0; b < 4; b++) acc[a][b] = 0.f;
            const float* Ab = A2t + 4 * r;
            const float* Bb = sWein + 4 * cg;
            #pragma unroll 4
            for (int k = 0; k < 128; k++) {
                float4 av = *(const float4*)(Ab + k * LDA);
                float4 bv = *(const float4*)(Bb + k * 64);
                acc[0][0] += av.x * bv.x; acc[0][1] += av.x * bv.y;
                acc[0][2] += av.x * bv.z; acc[0][3] += av.x * bv.w;
                acc[1][0] += av.y * bv.x; acc[1][1] += av.y * bv.y;
                acc[1][2] += av.y * bv.z; acc[1][3] += av.y * bv.w;
                acc[2][0] += av.z * bv.x; acc[2][1] += av.z * bv.y;
                acc[2][2] += av.z * bv.z; acc[2][3] += av.z * bv.w;
                acc[3][0] += av.w * bv.x; acc[3][1] += av.w * bv.y;
                acc[3][2] += av.w * bv.z; acc[3][3] += av.w * bv.w;
            }
            #pragma unroll
            for (int oo = 0; oo < 4; oo++) {
                int ko = 4 * cg + oo;
                float bias = sbein[ko];
                float muk = E0c + ko * MUSTEP;
                #pragma unroll
                for (int ee = 0; ee < 4; ee++) {
                    int e = 4 * r + ee;
                    float res;
                    if (ko < 50) {
                        float tt = sed[e] - muk;
                        res = expf(-BETAc * tt * tt) * (acc[ee][oo] + bias);
                    } else if (ko == 50) {
                        res = sd[e];
                    } else {
                        res = 0.f;
                    }
                    A2t[(128 + ko) * LDA + e] = res;
                }
            }
        }
        __syncthreads();

        // ---- GEMM2: [128e,192] @ W_eo1[192,64] -> silu -> Ht rows 0..63 ----
        {
            float acc[4][4];
            #pragma unroll
            for (int a = 0; a < 4; a++)
                #pragma unroll
                for (int b = 0; b < 4; b++) acc[a][b] = 0.f;
            const float* Ab = A2t + 4 * r;
            const float* Bb = sWeo1 + 4 * cg;
            #pragma unroll 4
            for (int k = 0; k < 192; k++) {
                float4 av = *(const float4*)(Ab + k * LDA);
                float4 bv = *(const float4*)(Bb + k * 64);
                acc[0][0] += av.x * bv.x; acc[0][1] += av.x * bv.y;
                acc[0][2] += av.x * bv.z; acc[0][3] += av.x * bv.w;
                acc[1][0] += av.y * bv.x; acc[1][1] += av.y * bv.y;
                acc[1][2] += av.y * bv.z; acc[1][3] += av.y * bv.w;
                acc[2][0] += av.z * bv.x; acc[2][1] += av.z * bv.y;
                acc[2][2] += av.z * bv.z; acc[2][3] += av.z * bv.w;
                acc[3][0] += av.w * bv.x; acc[3][1] += av.w * bv.y;
                acc[3][2] += av.w * bv.z; acc[3][3] += av.w * bv.w;
            }
            __syncthreads();  // all reads of A2t done before overwrite
            #pragma unroll
            for (int oo = 0; oo < 4; oo++) {
                int ko = 4 * cg + oo;
                float bias = sbeo1[ko];
                #pragma unroll
                for (int ee = 0; ee < 4; ee++) {
                    int e = 4 * r + ee;
                    A2t[ko * LDA + e] = siluf(acc[ee][oo] + bias);
                }
            }
        }
        __syncthreads();

        // ---- GEMM3: [128e,64] @ W_eo2[64,32] -> Ce rows 64..95 ----
        float* Ce = A2t + 64 * LDA;   // [32][LDA]
        {
            float acc[8];
            #pragma unroll
            for (int a = 0; a < 8; a++) acc[a] = 0.f;
            const float* Ab = A2t + 8 * r2;
            const float* Bb = sWeo2 + c2;
            #pragma unroll 4
            for (int k = 0; k < 64; k++) {
                float4 a0 = *(const float4*)(Ab + k * LDA);
                float4 a1 = *(const float4*)(Ab + k * LDA + 4);
                float bb = Bb[k * 32];
                acc[0] += a0.x * bb; acc[1] += a0.y * bb;
                acc[2] += a0.z * bb; acc[3] += a0.w * bb;
                acc[4] += a1.x * bb; acc[5] += a1.y * bb;
                acc[6] += a1.z * bb; acc[7] += a1.w * bb;
            }
            float bias = sbeo2[c2];
            #pragma unroll
            for (int ee = 0; ee < 8; ee++)
                Ce[c2 * LDA + 8 * r2 + ee] = acc[ee] + bias;   // rows 64..95, no Ht overlap
        }
        __syncthreads();

        // ---- store g_hedge (coalesced) ----
        #pragma unroll
        for (int it = 0; it < 8; it++) {
            int t = tid + it * 512;
            int e = t >> 5, m = t & 31;
            if (p0 + e < P) g_hedge[(size_t)(p0 + e) * 32 + m] = Ce[m * LDA + e];
        }

        // ---- attention heads: celu(Ce @ W_att + b), atomics ----
        {
            int p = p0 + ea;
            float a = sbatt[hh];
            #pragma unroll 8
            for (int m = 0; m < 32; m++)
                a += Ce[m * LDA + ea] * sWatt[m * 4 + hh];
            if (p < P) {
                float av = celu2f(a);
                ((float*)&g_att[p])[hh] = av;
                int i = si[ea];
                atomicMaxF((float*)&g_smax[i] + hh, av);
                if (hh == 0) atomicAdd(&g_cnt[i], 1.f);
            }
        }
    }
}

// ---------------- kernel B: exp(att - max) and segment sums ----------------
__global__ void kB(const int* __restrict__ idx_i, int P) {
    int p = blockIdx.x * blockDim.x + threadIdx.x;
    if (p >= P) return;
    int i = idx_i[p];
    float4 a = g_att[p];
    float4 m = g_smax[i];
    float4 e = make_float4(expf(a.x - m.x), expf(a.y - m.y),
                           expf(a.z - m.z), expf(a.w - m.w));
    g_att[p] = e;
    redAddV4((float*)&g_ssum[i], e);
}

// ---------------- kernel C: h_ij_sem scatter + spatial comb scatter ----------------
__global__ void kC(const int* __restrict__ idx_i, const float* __restrict__ W_xm, int P) {
    __shared__ float sWxm[4096];
    __shared__ float sHs[8][2][128];
    int tid = threadIdx.x;
    for (int t = tid; t < 4096; t += blockDim.x) sWxm[t] = W_xm[t];
    __syncthreads();

    int lane = tid & 31, w = tid >> 5;
    int gw = blockIdx.x * (blockDim.x >> 5) + w;
    int nwarp = gridDim.x * (blockDim.x >> 5);
    int nPair = (P + 1) >> 1;

    for (int q = gw; q < nPair; q += nwarp) {
        int p0 = 2 * q, p1 = 2 * q + 1;
        bool v1 = (p1 < P);

        int i0 = idx_i[p0];
        float he0 = g_hedge[(size_t)p0 * 32 + lane];
        float4 e0 = g_att[p0];
        float4 s0 = g_ssum[i0];
        float4 hv0 = make_float4(he0 * (e0.x / s0.x), he0 * (e0.y / s0.y),
                                 he0 * (e0.z / s0.z), he0 * (e0.w / s0.w));
        ((float4*)sHs[w][0])[lane] = hv0;
        redAddV4((float*)&g_hisem[(size_t)i0 * 32 + lane], hv0);

        int i1 = i0;
        if (v1) {
            i1 = idx_i[p1];
            float he1 = g_hedge[(size_t)p1 * 32 + lane];
            float4 e1 = g_att[p1];
            float4 s1 = g_ssum[i1];
            float4 hv1 = make_float4(he1 * (e1.x / s1.x), he1 * (e1.y / s1.y),
                                     he1 * (e1.z / s1.z), he1 * (e1.w / s1.w));
            ((float4*)sHs[w][1])[lane] = hv1;
            redAddV4((float*)&g_hisem[(size_t)i1 * 32 + lane], hv1);
        }
        __syncwarp();

        float acc0 = 0.f, acc1 = 0.f;
        #pragma unroll 8
        for (int m = 0; m < 128; m++) {
            float wv = sWxm[m * 32 + lane];
            acc0 += sHs[w][0][m] * wv;
            acc1 += sHs[w][1][m] * wv;
        }
        float t0 = tanhf(acc0);
        float4 dd0 = g_dird[p0];
        atomicAdd(&g_comb[(size_t)i0 * 96 + lane],      t0 * dd0.x);
        atomicAdd(&g_comb[(size_t)i0 * 96 + 32 + lane], t0 * dd0.y);
        atomicAdd(&g_comb[(size_t)i0 * 96 + 64 + lane], t0 * dd0.z);
        if (v1) {
            float t1 = tanhf(acc1);
            float4 dd1 = g_dird[p1];
            atomicAdd(&g_comb[(size_t)i1 * 96 + lane],      t1 * dd1.x);
            atomicAdd(&g_comb[(size_t)i1 * 96 + 32 + lane], t1 * dd1.y);
            atomicAdd(&g_comb[(size_t)i1 * 96 + 64 + lane], t1 * dd1.z);
        }
        __syncwarp();
    }
}

// ---------------- kernel D: per-node MLPs + outputs (warp per node) ----------------
#define SMD_FLOATS (2048 + 64 + 4096 + 64 + 16384 + 64 + 4096 + 64 + 4096 + 64 + 64 + 32 + 8*256 + 8*64 + 8*32)

__global__ void kD(const float* __restrict__ h, const float* __restrict__ x, const float* __restrict__ v,
                   const float* __restrict__ W_pn1, const float* __restrict__ b_pn1,
                   const float* __restrict__ W_pn2, const float* __restrict__ b_pn2,
                   const float* __restrict__ W_n1, const float* __restrict__ b_n1,
                   const float* __restrict__ W_n2, const float* __restrict__ b_n2,
                   const float* __restrict__ W_v1, const float* __restrict__ b_v1,
                   const float* __restrict__ W_v2, const float* __restrict__ W_vm,
                   float* __restrict__ out, int N)
{
    extern __shared__ float sm[];
    float* sWpn1 = sm;              // 2048
    float* sbpn1 = sWpn1 + 2048;    // 64
    float* sWpn2 = sbpn1 + 64;      // 4096
    float* sbpn2 = sWpn2 + 4096;    // 64
    float* sWn1  = sbpn2 + 64;      // 16384
    float* sbn1  = sWn1 + 16384;    // 64
    float* sWn2  = sbn1 + 64;       // 4096
    float* sbn2  = sWn2 + 4096;     // 64
    float* sWv1  = sbn2 + 64;       // 4096
    float* sbv1  = sWv1 + 4096;     // 64
    float* sWv2  = sbv1 + 64;       // 64
    float* sWvm  = sWv2 + 64;       // 32
    float* sNin  = sWvm + 32;       // 8*256
    float* sHidw = sNin + 8 * 256;  // 8*64
    float* sSn   = sHidw + 8 * 64;  // 8*32

    int tid = threadIdx.x;
    for (int t = tid; t < 2048; t += blockDim.x) sWpn1[t] = W_pn1[t];
    for (int t = tid; t < 4096; t += blockDim.x) sWpn2[t] = W_pn2[t];
    for (int t = tid; t < 16384; t += blockDim.x) sWn1[t] = W_n1[t];
    for (int t = tid; t < 4096; t += blockDim.x) sWn2[t] = W_n2[t];
    for (int t = tid; t < 4096; t += blockDim.x) sWv1[t] = W_v1[t];
    for (int t = tid; t < 64; t += blockDim.x) {
        sbpn1[t] = b_pn1[t]; sbpn2[t] = b_pn2[t]; sbn1[t] = b_n1[t];
        sbn2[t] = b_n2[t]; sbv1[t] = b_v1[t]; sWv2[t] = W_v2[t];
    }
    for (int t = tid; t < 32; t += blockDim.x) sWvm[t] = W_vm[t];
    __syncthreads();

    int lane = tid & 31, w = tid >> 5;
    float* nin  = sNin + w * 256;
    float* hidw = sHidw + w * 64;
    float* sn   = sSn + w * 32;
    int gw = blockIdx.x * (blockDim.x >> 5) + w;
    int nwarp = gridDim.x * (blockDim.x >> 5);

    for (int i = gw; i < N; i += nwarp) {
        float inv = 1.f / fmaxf(g_cnt[i], 1.f);
        float cm0 = g_comb[(size_t)i * 96 + lane] * inv;
        float cm1 = g_comb[(size_t)i * 96 + 32 + lane] * inv;
        float cm2 = g_comb[(size_t)i * 96 + 64 + lane] * inv;
        sn[lane] = cm0 * cm0 + cm1 * cm1 + cm2 * cm2;
        __syncwarp();

        // spatial MLP: 32 -> 64 -> 64 (silu, silu)
        float a0 = sbpn1[lane], a1 = sbpn1[lane + 32];
        #pragma unroll
        for (int m = 0; m < 32; m++) {
            float vv = sn[m];
            a0 += vv * sWpn1[m * 64 + lane];
            a1 += vv * sWpn1[m * 64 + lane + 32];
        }
        hidw[lane] = siluf(a0); hidw[lane + 32] = siluf(a1);
        __syncwarp();
        a0 = sbpn2[lane]; a1 = sbpn2[lane + 32];
        #pragma unroll 8
        for (int m = 0; m < 64; m++) {
            float vv = hidw[m];
            a0 += vv * sWpn2[m * 64 + lane];
            a1 += vv * sWpn2[m * 64 + lane + 32];
        }
        nin[192 + lane] = siluf(a0); nin[192 + lane + 32] = siluf(a1);

        float h0 = h[(size_t)i * 64 + lane], h1 = h[(size_t)i * 64 + lane + 32];
        nin[lane] = h0; nin[lane + 32] = h1;
        ((float4*)(nin + 64))[lane] = g_hisem[(size_t)i * 32 + lane];
        __syncwarp();

        // node MLP: 256 -> 64 -> 64
        a0 = sbn1[lane]; a1 = sbn1[lane + 32];
        #pragma unroll 8
        for (int m = 0; m < 256; m++) {
            float vv = nin[m];
            a0 += vv * sWn1[m * 64 + lane];
            a1 += vv * sWn1[m * 64 + lane + 32];
        }
        hidw[lane] = siluf(a0); hidw[lane + 32] = siluf(a1);
        __syncwarp();
        a0 = sbn2[lane]; a1 = sbn2[lane + 32];
        #pragma unroll 8
        for (int m = 0; m < 64; m++) {
            float vv = hidw[m];
            a0 += vv * sWn2[m * 64 + lane];
            a1 += vv * sWn2[m * 64 + lane + 32];
        }
        float hn0 = h0 + siluf(a0), hn1 = h1 + siluf(a1);
        out[(size_t)i * 64 + lane] = hn0;
        out[(size_t)i * 64 + lane + 32] = hn1;
        __syncwarp();
        nin[lane] = hn0; nin[lane + 32] = hn1;
        __syncwarp();

        // gate MLP: 64 -> 64 -> 1 ; 2*sigmoid
        a0 = sbv1[lane]; a1 = sbv1[lane + 32];
        #pragma unroll 8
        for (int m = 0; m < 64; m++) {
            float vv = nin[m];
            a0 += vv * sWv1[m * 64 + lane];
            a1 += vv * sWv1[m * 64 + lane + 32];
        }
        float part = siluf(a0) * sWv2[lane] + siluf(a1) * sWv2[lane + 32];
        float q0 = cm0 * sWvm[lane], q1 = cm1 * sWvm[lane], q2 = cm2 * sWvm[lane];
        #pragma unroll
        for (int o = 16; o; o >>= 1) {
            part += __shfl_xor_sync(0xffffffffu, part, o);
            q0 += __shfl_xor_sync(0xffffffffu, q0, o);
            q1 += __shfl_xor_sync(0xffffffffu, q1, o);
            q2 += __shfl_xor_sync(0xffffffffu, q2, o);
        }
        float gate = 2.f / (1.f + expf(-part));
        if (lane < 3) {
            float dv = (lane == 0) ? q0 : ((lane == 1) ? q1 : q2);
            float vn = gate * v[(size_t)i * 3 + lane] + dv;
            out[(size_t)N * 64 + (size_t)i * 3 + lane] = x[(size_t)i * 3 + lane] + vn;
            out[(size_t)N * 67 + (size_t)i * 3 + lane] = vn;
        }
        __syncwarp();
    }
}

// ---------------- launch ----------------
extern "C" void kernel_launch(void* const* d_in, const int* in_sizes, int n_in,
                              void* d_out, int out_size) {
    const float* h     = (const float*)d_in[0];
    const float* x     = (const float*)d_in[1];
    const float* v     = (const float*)d_in[2];
    const int*   idx_i = (const int*)d_in[3];
    const int*   idx_j = (const int*)d_in[4];
    const float* W_ein = (const float*)d_in[5];
    const float* b_ein = (const float*)d_in[6];
    const float* W_eo1 = (const float*)d_in[7];
    const float* b_eo1 = (const float*)d_in[8];
    const float* W_eo2 = (const float*)d_in[9];
    const float* b_eo2 = (const float*)d_in[10];
    const float* W_att = (const float*)d_in[11];
    const float* b_att = (const float*)d_in[12];
    const float* W_xm  = (const float*)d_in[13];
    const float* W_vm  = (const float*)d_in[14];
    const float* W_pn1 = (const float*)d_in[15];
    const float* b_pn1 = (const float*)d_in[16];
    const float* W_pn2 = (const float*)d_in[17];
    const float* b_pn2 = (const float*)d_in[18];
    const float* W_n1  = (const float*)d_in[19];
    const float* b_n1  = (const float*)d_in[20];
    const float* W_n2  = (const float*)d_in[21];
    const float* b_n2  = (const float*)d_in[22];
    const float* W_v1  = (const float*)d_in[23];
    const float* b_v1  = (const float*)d_in[24];
    const float* W_v2  = (const float*)d_in[25];
    float* out = (float*)d_out;

    int N = in_sizes[0] / 64;
    int P = in_sizes[3];

    size_t smA = (size_t)SMA_FLOATS * sizeof(float);  // 194240 B
    size_t smD = (size_t)SMD_FLOATS * sizeof(float);  // 135808 B
    cudaFuncSetAttribute(kA, cudaFuncAttributeMaxDynamicSharedMemorySize, (int)smA);
    cudaFuncSetAttribute(kD, cudaFuncAttributeMaxDynamicSharedMemorySize, (int)smD);

    kInit<<<(N * 128 + 255) / 256, 256>>>(N);
    kA<<<148, 512, smA>>>(h, x, idx_i, idx_j, W_ein, b_ein, W_eo1, b_eo1,
                          W_eo2, b_eo2, W_att, b_att, P);
    kB<<<(P + 255) / 256, 256>>>(idx_i, P);
    kC<<<608, 256>>>(idx_i, W_xm, P);
    kD<<<152, 256, smD>>>(h, x, v, W_pn1, b_pn1, W_pn2, b_pn2, W_n1, b_n1,
                          W_n2, b_n2, W_v1, b_v1, W_v2, W_vm, out, N);
}

// round 13
// speedup vs baseline: 1.0014x; 1.0014x over previous
#include <cuda_runtime.h>
#include <math.h>
#include <stdint.h>

// Problem constants (fixed by the dataset)
#define NMAX 25000
#define PMAX 400000

// ---------------- scratch (static device globals; no allocs) ----------------
__device__ float  g_hedge[(size_t)PMAX * 32];   // per-edge edge features [P,32]
__device__ float4 g_att[PMAX];                  // att (then exp(att-max)) [P,4]
__device__ float4 g_dird[PMAX];                 // dir.x,dir.y,dir.z,d
__device__ float4 g_hisem[(size_t)NMAX * 32];   // h_i_sem [N,128] as float4
__device__ float  g_comb[(size_t)NMAX * 96];    // comb_sum [N][3][32]
__device__ float4 g_smax[NMAX];                 // segment max of att [N,4]
__device__ float4 g_ssum[NMAX];                 // segment sum of exp [N,4]
__device__ float  g_cnt[NMAX];                  // edges per receiver

// ---------------- math helpers ----------------
__device__ __forceinline__ float siluf(float x) { return x / (1.f + expf(-x)); }
__device__ __forceinline__ float celu2f(float x) { return x > 0.f ? x : 2.f * expm1f(0.5f * x); }

__device__ __forceinline__ void atomicMaxF(float* addr, float val) {
    int* ia = (int*)addr;
    int old = *ia;
    while (__int_as_float(old) < val) {
        int assumed = old;
        old = atomicCAS(ia, assumed, __float_as_int(val));
        if (old == assumed) break;
    }
}

__device__ __forceinline__ void redAddV4(float* addr, float4 v) {
    asm volatile("red.global.add.v4.f32 [%0], {%1,%2,%3,%4};"
                 :: "l"(addr), "f"(v.x), "f"(v.y), "f"(v.z), "f"(v.w) : "memory");
}

// PhysNet RBF constants
constexpr double E0d = 0.6065306597126334;
constexpr float  E0c = (float)E0d;
constexpr float  MUSTEP = (float)((1.0 - E0d) / 49.0);
constexpr float  BETAc = (float)(1.0 / ((0.04 * (1.0 - E0d)) * (0.04 * (1.0 - E0d))));

// ---------------- kernel 0: init accumulators ----------------
__global__ void kInit(int N) {
    int t = blockIdx.x * blockDim.x + threadIdx.x;
    if (t < N * 128) ((float*)g_hisem)[t] = 0.f;
    if (t < N * 96)  g_comb[t] = 0.f;
    if (t < N * 4) {
        ((float*)g_smax)[t] = __int_as_float(0xff800000); // -inf
        ((float*)g_ssum)[t] = 0.f;
    }
    if (t < N) g_cnt[t] = 0.f;
}

// ---------------- kernel A: per-edge MLPs as tiled GEMMs ----------------
// Tile = 128 edges, 512 threads/block, persistent over tiles.
// smem layout (floats):
#define LDA 132
#define OFF_WEIN  0                     // [128][64]  = 8192
#define OFF_WEO1  8192                  // [192][64]  = 12288
#define OFF_WEO2  20480                 // [64][32]   = 2048
#define OFF_WATT  22528                 // [32][4]    = 128
#define OFF_BEIN  22656                 // 64
#define OFF_BEO1  22720                 // 64
#define OFF_BEO2  22784                 // 32
#define OFF_BATT  22816                 // 16 (4 used)
#define OFF_SD    22832                 // 128
#define OFF_SED   22960                 // 128
#define OFF_SI    23088                 // 128 (ints)
#define OFF_A2T   23216                 // [192][132] = 25344
#define SMA_FLOATS (23216 + 192 * LDA)  // 48560 floats = 194240 B

__global__ void __launch_bounds__(512, 1)
kA(const float* __restrict__ h, const float* __restrict__ x,
   const int* __restrict__ idx_i, const int* __restrict__ idx_j,
   const float* __restrict__ W_ein, const float* __restrict__ b_ein,
   const float* __restrict__ W_eo1, const float* __restrict__ b_eo1,
   const float* __restrict__ W_eo2, const float* __restrict__ b_eo2,
   const float* __restrict__ W_att, const float* __restrict__ b_att,
   int P)
{
    extern __shared__ float sm[];
    float* sWein = sm + OFF_WEIN;
    float* sWeo1 = sm + OFF_WEO1;
    float* sWeo2 = sm + OFF_WEO2;
    float* sWatt = sm + OFF_WATT;
    float* sbein = sm + OFF_BEIN;
    float* sbeo1 = sm + OFF_BEO1;
    float* sbeo2 = sm + OFF_BEO2;
    float* sbatt = sm + OFF_BATT;
    float* sd    = sm + OFF_SD;
    float* sed   = sm + OFF_SED;
    int*   si    = (int*)(sm + OFF_SI);
    float* A2t   = sm + OFF_A2T;

    const int tid = threadIdx.x;

    // load weights once per block
    for (int t = tid; t < 8192; t += 512) {
        int m = t >> 6, k = t & 63;
        sWein[t] = (k < 50) ? W_ein[m * 50 + k] : 0.f;
    }
    for (int t = tid; t < 12288; t += 512) {
        int m = t >> 6;
        sWeo1[t] = (m < 179) ? W_eo1[t] : 0.f;
    }
    for (int t = tid; t < 2048; t += 512) sWeo2[t] = W_eo2[t];
    if (tid < 128) sWatt[tid] = W_att[tid];
    if (tid < 64)  sbein[tid] = (tid < 50) ? b_ein[tid] : 0.f;
    if (tid < 64)  sbeo1[tid] = b_eo1[tid];
    if (tid < 32)  sbeo2[tid] = b_eo2[tid];
    if (tid < 4)   sbatt[tid] = b_att[tid];

    const int numTiles = (P + 127) >> 7;
    const int r  = tid & 31;   // edge group (4 edges) for GEMM1/2
    const int cg = tid >> 5;   // out group (4 outs)
    const int r2 = tid & 15;   // edge group (8 edges) for GEMM3
    const int c2 = tid >> 4;   // out (1 of 32)
    const int ea = tid >> 2;   // edge for att phase
    const int hh = tid & 3;    // head for att phase

    for (int tile = blockIdx.x; tile < numTiles; tile += gridDim.x) {
        const int p0 = tile << 7;
        __syncthreads();   // previous tile fully consumed

        // ---- gather: build A2t rows 0..127 (h_cat transposed), geometry ----
        {
            int e = tid >> 2, q = tid & 3;
            int p = p0 + e;
            int i = 0, j = 0;
            bool valid = (p < P);
            if (valid) { i = idx_i[p]; j = idx_j[p]; }
            if (q == 0) {
                if (valid) {
                    si[e] = i;
                    float rx = x[3 * j]     - x[3 * i];
                    float ry = x[3 * j + 1] - x[3 * i + 1];
                    float rz = x[3 * j + 2] - x[3 * i + 2];
                    float d = sqrtf(rx * rx + ry * ry + rz * rz + 1e-8f);
                    float invd = 1.f / (d + 1e-8f);
                    g_dird[p] = make_float4(rx * invd, ry * invd, rz * invd, d);
                    sd[e] = d;
                    sed[e] = expf(-d);
                } else {
                    si[e] = 0; sd[e] = 0.f; sed[e] = 1.f;
                }
            }
            const float* hi = h + (size_t)i * 64 + q * 16;
            const float* hj = h + (size_t)j * 64 + q * 16;
            #pragma unroll
            for (int kk = 0; kk < 16; kk++) {
                float v0 = valid ? hi[kk] : 0.f;
                float v1 = valid ? hj[kk] : 0.f;
                A2t[(q * 16 + kk) * LDA + e]      = v0;
                A2t[(64 + q * 16 + kk) * LDA + e] = v1;
            }
        }
        __syncthreads();

        // ---- GEMM1: [128e,128] @ W_ein[128,64] -> filtered rows 128..191 ----
        {
            float acc[4][4];
            #pragma unroll
            for (int a = 0; a < 4; a++)
                #pragma unroll
                for (int b = 0; b < 4; b++) acc[a][b] = 0.f;
            const float* Ab = A2t + 4 * r;
            const float* Bb = sWein + 4 * cg;
            #pragma unroll 4
            for (int k = 0; k < 128; k++) {
                float4 av = *(const float4*)(Ab + k * LDA);
                float4 bv = *(const float4*)(Bb + k * 64);
                acc[0][0] += av.x * bv.x; acc[0][1] += av.x * bv.y;
                acc[0][2] += av.x * bv.z; acc[0][3] += av.x * bv.w;
                acc[1][0] += av.y * bv.x; acc[1][1] += av.y * bv.y;
                acc[1][2] += av.y * bv.z; acc[1][3] += av.y * bv.w;
                acc[2][0] += av.z * bv.x; acc[2][1] += av.z * bv.y;
                acc[2][2] += av.z * bv.z; acc[2][3] += av.z * bv.w;
                acc[3][0] += av.w * bv.x; acc[3][1] += av.w * bv.y;
                acc[3][2] += av.w * bv.z; acc[3][3] += av.w * bv.w;
            }
            #pragma unroll
            for (int oo = 0; oo < 4; oo++) {
                int ko = 4 * cg + oo;
                float bias = sbein[ko];
                float muk = E0c + ko * MUSTEP;
                #pragma unroll
                for (int ee = 0; ee < 4; ee++) {
                    int e = 4 * r + ee;
                    float res;
                    if (ko < 50) {
                        float tt = sed[e] - muk;
                        res = expf(-BETAc * tt * tt) * (acc[ee][oo] + bias);
                    } else if (ko == 50) {
                        res = sd[e];
                    } else {
                        res = 0.f;
                    }
                    A2t[(128 + ko) * LDA + e] = res;
                }
            }
        }
        __syncthreads();

        // ---- GEMM2: [128e,192] @ W_eo1[192,64] -> silu -> Ht rows 0..63 ----
        {
            float acc[4][4];
            #pragma unroll
            for (int a = 0; a < 4; a++)
                #pragma unroll
                for (int b = 0; b < 4; b++) acc[a][b] = 0.f;
            const float* Ab = A2t + 4 * r;
            const float* Bb = sWeo1 + 4 * cg;
            #pragma unroll 4
            for (int k = 0; k < 192; k++) {
                float4 av = *(const float4*)(Ab + k * LDA);
                float4 bv = *(const float4*)(Bb + k * 64);
                acc[0][0] += av.x * bv.x; acc[0][1] += av.x * bv.y;
                acc[0][2] += av.x * bv.z; acc[0][3] += av.x * bv.w;
                acc[1][0] += av.y * bv.x; acc[1][1] += av.y * bv.y;
                acc[1][2] += av.y * bv.z; acc[1][3] += av.y * bv.w;
                acc[2][0] += av.z * bv.x; acc[2][1] += av.z * bv.y;
                acc[2][2] += av.z * bv.z; acc[2][3] += av.z * bv.w;
                acc[3][0] += av.w * bv.x; acc[3][1] += av.w * bv.y;
                acc[3][2] += av.w * bv.z; acc[3][3] += av.w * bv.w;
            }
            __syncthreads();  // all reads of A2t done before overwrite
            #pragma unroll
            for (int oo = 0; oo < 4; oo++) {
                int ko = 4 * cg + oo;
                float bias = sbeo1[ko];
                #pragma unroll
                for (int ee = 0; ee < 4; ee++) {
                    int e = 4 * r + ee;
                    A2t[ko * LDA + e] = siluf(acc[ee][oo] + bias);
                }
            }
        }
        __syncthreads();

        // ---- GEMM3: [128e,64] @ W_eo2[64,32] -> Ce rows 64..95 ----
        float* Ce = A2t + 64 * LDA;   // [32][LDA]
        {
            float acc[8];
            #pragma unroll
            for (int a = 0; a < 8; a++) acc[a] = 0.f;
            const float* Ab = A2t + 8 * r2;
            const float* Bb = sWeo2 + c2;
            #pragma unroll 4
            for (int k = 0; k < 64; k++) {
                float4 a0 = *(const float4*)(Ab + k * LDA);
                float4 a1 = *(const float4*)(Ab + k * LDA + 4);
                float bb = Bb[k * 32];
                acc[0] += a0.x * bb; acc[1] += a0.y * bb;
                acc[2] += a0.z * bb; acc[3] += a0.w * bb;
                acc[4] += a1.x * bb; acc[5] += a1.y * bb;
                acc[6] += a1.z * bb; acc[7] += a1.w * bb;
            }
            float bias = sbeo2[c2];
            #pragma unroll
            for (int ee = 0; ee < 8; ee++)
                Ce[c2 * LDA + 8 * r2 + ee] = acc[ee] + bias;   // rows 64..95, no Ht overlap
        }
        __syncthreads();

        // ---- store g_hedge (coalesced) ----
        #pragma unroll
        for (int it = 0; it < 8; it++) {
            int t = tid + it * 512;
            int e = t >> 5, m = t & 31;
            if (p0 + e < P) g_hedge[(size_t)(p0 + e) * 32 + m] = Ce[m * LDA + e];
        }

        // ---- attention heads: celu(Ce @ W_att + b), atomics ----
        {
            int p = p0 + ea;
            float a = sbatt[hh];
            #pragma unroll 8
            for (int m = 0; m < 32; m++)
                a += Ce[m * LDA + ea] * sWatt[m * 4 + hh];
            if (p < P) {
                float av = celu2f(a);
                ((float*)&g_att[p])[hh] = av;
                int i = si[ea];
                atomicMaxF((float*)&g_smax[i] + hh, av);
                if (hh == 0) atomicAdd(&g_cnt[i], 1.f);
            }
        }
    }
}

// ---------------- kernel B: exp(att - max) and segment sums ----------------
__global__ void kB(const int* __restrict__ idx_i, int P) {
    int p = blockIdx.x * blockDim.x + threadIdx.x;
    if (p >= P) return;
    int i = idx_i[p];
    float4 a = g_att[p];
    float4 m = g_smax[i];
    float4 e = make_float4(expf(a.x - m.x), expf(a.y - m.y),
                           expf(a.z - m.z), expf(a.w - m.w));
    g_att[p] = e;
    redAddV4((float*)&g_ssum[i], e);
}

// ---------------- kernel C: h_ij_sem scatter + spatial comb scatter ----------------
__global__ void kC(const int* __restrict__ idx_i, const float* __restrict__ W_xm, int P) {
    __shared__ float sWxm[4096];
    __shared__ float sHs[8][2][128];
    int tid = threadIdx.x;
    for (int t = tid; t < 4096; t += blockDim.x) sWxm[t] = W_xm[t];
    __syncthreads();

    int lane = tid & 31, w = tid >> 5;
    int gw = blockIdx.x * (blockDim.x >> 5) + w;
    int nwarp = gridDim.x * (blockDim.x >> 5);
    int nPair = (P + 1) >> 1;

    for (int q = gw; q < nPair; q += nwarp) {
        int p0 = 2 * q, p1 = 2 * q + 1;
        bool v1 = (p1 < P);

        int i0 = idx_i[p0];
        float he0 = g_hedge[(size_t)p0 * 32 + lane];
        float4 e0 = g_att[p0];
        float4 s0 = g_ssum[i0];
        float4 hv0 = make_float4(he0 * (e0.x / s0.x), he0 * (e0.y / s0.y),
                                 he0 * (e0.z / s0.z), he0 * (e0.w / s0.w));
        ((float4*)sHs[w][0])[lane] = hv0;
        redAddV4((float*)&g_hisem[(size_t)i0 * 32 + lane], hv0);

        int i1 = i0;
        if (v1) {
            i1 = idx_i[p1];
            float he1 = g_hedge[(size_t)p1 * 32 + lane];
            float4 e1 = g_att[p1];
            float4 s1 = g_ssum[i1];
            float4 hv1 = make_float4(he1 * (e1.x / s1.x), he1 * (e1.y / s1.y),
                                     he1 * (e1.z / s1.z), he1 * (e1.w / s1.w));
            ((float4*)sHs[w][1])[lane] = hv1;
            redAddV4((float*)&g_hisem[(size_t)i1 * 32 + lane], hv1);
        }
        __syncwarp();

        float acc0 = 0.f, acc1 = 0.f;
        #pragma unroll 8
        for (int m = 0; m < 128; m++) {
            float wv = sWxm[m * 32 + lane];
            acc0 += sHs[w][0][m] * wv;
            acc1 += sHs[w][1][m] * wv;
        }
        float t0 = tanhf(acc0);
        float4 dd0 = g_dird[p0];
        atomicAdd(&g_comb[(size_t)i0 * 96 + lane],      t0 * dd0.x);
        atomicAdd(&g_comb[(size_t)i0 * 96 + 32 + lane], t0 * dd0.y);
        atomicAdd(&g_comb[(size_t)i0 * 96 + 64 + lane], t0 * dd0.z);
        if (v1) {
            float t1 = tanhf(acc1);
            float4 dd1 = g_dird[p1];
            atomicAdd(&g_comb[(size_t)i1 * 96 + lane],      t1 * dd1.x);
            atomicAdd(&g_comb[(size_t)i1 * 96 + 32 + lane], t1 * dd1.y);
            atomicAdd(&g_comb[(size_t)i1 * 96 + 64 + lane], t1 * dd1.z);
        }
        __syncwarp();
    }
}

// ---------------- kernel D: per-node MLPs + outputs (warp per node) ----------------
#define SMD_FLOATS (2048 + 64 + 4096 + 64 + 16384 + 64 + 4096 + 64 + 4096 + 64 + 64 + 32 + 8*256 + 8*64 + 8*32)

__global__ void kD(const float* __restrict__ h, const float* __restrict__ x, const float* __restrict__ v,
                   const float* __restrict__ W_pn1, const float* __restrict__ b_pn1,
                   const float* __restrict__ W_pn2, const float* __restrict__ b_pn2,
                   const float* __restrict__ W_n1, const float* __restrict__ b_n1,
                   const float* __restrict__ W_n2, const float* __restrict__ b_n2,
                   const float* __restrict__ W_v1, const float* __restrict__ b_v1,
                   const float* __restrict__ W_v2, const float* __restrict__ W_vm,
                   float* __restrict__ out, int N)
{
    extern __shared__ float sm[];
    float* sWpn1 = sm;              // 2048
    float* sbpn1 = sWpn1 + 2048;    // 64
    float* sWpn2 = sbpn1 + 64;      // 4096
    float* sbpn2 = sWpn2 + 4096;    // 64
    float* sWn1  = sbpn2 + 64;      // 16384
    float* sbn1  = sWn1 + 16384;    // 64
    float* sWn2  = sbn1 + 64;       // 4096
    float* sbn2  = sWn2 + 4096;     // 64
    float* sWv1  = sbn2 + 64;       // 4096
    float* sbv1  = sWv1 + 4096;     // 64
    float* sWv2  = sbv1 + 64;       // 64
    float* sWvm  = sWv2 + 64;       // 32
    float* sNin  = sWvm + 32;       // 8*256
    float* sHidw = sNin + 8 * 256;  // 8*64
    float* sSn   = sHidw + 8 * 64;  // 8*32

    int tid = threadIdx.x;
    for (int t = tid; t < 2048; t += blockDim.x) sWpn1[t] = W_pn1[t];
    for (int t = tid; t < 4096; t += blockDim.x) sWpn2[t] = W_pn2[t];
    for (int t = tid; t < 16384; t += blockDim.x) sWn1[t] = W_n1[t];
    for (int t = tid; t < 4096; t += blockDim.x) sWn2[t] = W_n2[t];
    for (int t = tid; t < 4096; t += blockDim.x) sWv1[t] = W_v1[t];
    for (int t = tid; t < 64; t += blockDim.x) {
        sbpn1[t] = b_pn1[t]; sbpn2[t] = b_pn2[t]; sbn1[t] = b_n1[t];
        sbn2[t] = b_n2[t]; sbv1[t] = b_v1[t]; sWv2[t] = W_v2[t];
    }
    for (int t = tid; t < 32; t += blockDim.x) sWvm[t] = W_vm[t];
    __syncthreads();

    int lane = tid & 31, w = tid >> 5;
    float* nin  = sNin + w * 256;
    float* hidw = sHidw + w * 64;
    float* sn   = sSn + w * 32;
    int gw = blockIdx.x * (blockDim.x >> 5) + w;
    int nwarp = gridDim.x * (blockDim.x >> 5);

    for (int i = gw; i < N; i += nwarp) {
        float inv = 1.f / fmaxf(g_cnt[i], 1.f);
        float cm0 = g_comb[(size_t)i * 96 + lane] * inv;
        float cm1 = g_comb[(size_t)i * 96 + 32 + lane] * inv;
        float cm2 = g_comb[(size_t)i * 96 + 64 + lane] * inv;
        sn[lane] = cm0 * cm0 + cm1 * cm1 + cm2 * cm2;
        __syncwarp();

        // spatial MLP: 32 -> 64 -> 64 (silu, silu)
        float a0 = sbpn1[lane], a1 = sbpn1[lane + 32];
        #pragma unroll
        for (int m = 0; m < 32; m++) {
            float vv = sn[m];
            a0 += vv * sWpn1[m * 64 + lane];
            a1 += vv * sWpn1[m * 64 + lane + 32];
        }
        hidw[lane] = siluf(a0); hidw[lane + 32] = siluf(a1);
        __syncwarp();
        a0 = sbpn2[lane]; a1 = sbpn2[lane + 32];
        #pragma unroll 8
        for (int m = 0; m < 64; m++) {
            float vv = hidw[m];
            a0 += vv * sWpn2[m * 64 + lane];
            a1 += vv * sWpn2[m * 64 + lane + 32];
        }
        nin[192 + lane] = siluf(a0); nin[192 + lane + 32] = siluf(a1);

        float h0 = h[(size_t)i * 64 + lane], h1 = h[(size_t)i * 64 + lane + 32];
        nin[lane] = h0; nin[lane + 32] = h1;
        ((float4*)(nin + 64))[lane] = g_hisem[(size_t)i * 32 + lane];
        __syncwarp();

        // node MLP: 256 -> 64 -> 64
        a0 = sbn1[lane]; a1 = sbn1[lane + 32];
        #pragma unroll 8
        for (int m = 0; m < 256; m++) {
            float vv = nin[m];
            a0 += vv * sWn1[m * 64 + lane];
            a1 += vv * sWn1[m * 64 + lane + 32];
        }
        hidw[lane] = siluf(a0); hidw[lane + 32] = siluf(a1);
        __syncwarp();
        a0 = sbn2[lane]; a1 = sbn2[lane + 32];
        #pragma unroll 8
        for (int m = 0; m < 64; m++) {
            float vv = hidw[m];
            a0 += vv * sWn2[m * 64 + lane];
            a1 += vv * sWn2[m * 64 + lane + 32];
        }
        float hn0 = h0 + siluf(a0), hn1 = h1 + siluf(a1);
        out[(size_t)i * 64 + lane] = hn0;
        out[(size_t)i * 64 + lane + 32] = hn1;
        __syncwarp();
        nin[lane] = hn0; nin[lane + 32] = hn1;
        __syncwarp();

        // gate MLP: 64 -> 64 -> 1 ; 2*sigmoid
        a0 = sbv1[lane]; a1 = sbv1[lane + 32];
        #pragma unroll 8
        for (int m = 0; m < 64; m++) {
            float vv = nin[m];
            a0 += vv * sWv1[m * 64 + lane];
            a1 += vv * sWv1[m * 64 + lane + 32];
        }
        float part = siluf(a0) * sWv2[lane] + siluf(a1) * sWv2[lane + 32];
        float q0 = cm0 * sWvm[lane], q1 = cm1 * sWvm[lane], q2 = cm2 * sWvm[lane];
        #pragma unroll
        for (int o = 16; o; o >>= 1) {
            part += __shfl_xor_sync(0xffffffffu, part, o);
            q0 += __shfl_xor_sync(0xffffffffu, q0, o);
            q1 += __shfl_xor_sync(0xffffffffu, q1, o);
            q2 += __shfl_xor_sync(0xffffffffu, q2, o);
        }
        float gate = 2.f / (1.f + expf(-part));
        if (lane < 3) {
            float dv = (lane == 0) ? q0 : ((lane == 1) ? q1 : q2);
            float vn = gate * v[(size_t)i * 3 + lane] + dv;
            out[(size_t)N * 64 + (size_t)i * 3 + lane] = x[(size_t)i * 3 + lane] + vn;
            out[(size_t)N * 67 + (size_t)i * 3 + lane] = vn;
        }
        __syncwarp();
    }
}

// ---------------- launch ----------------
extern "C" void kernel_launch(void* const* d_in, const int* in_sizes, int n_in,
                              void* d_out, int out_size) {
    const float* h     = (const float*)d_in[0];
    const float* x     = (const float*)d_in[1];
    const float* v     = (const float*)d_in[2];
    const int*   idx_i = (const int*)d_in[3];
    const int*   idx_j = (const int*)d_in[4];
    const float* W_ein = (const float*)d_in[5];
    const float* b_ein = (const float*)d_in[6];
    const float* W_eo1 = (const float*)d_in[7];
    const float* b_eo1 = (const float*)d_in[8];
    const float* W_eo2 = (const float*)d_in[9];
    const float* b_eo2 = (const float*)d_in[10];
    const float* W_att = (const float*)d_in[11];
    const float* b_att = (const float*)d_in[12];
    const float* W_xm  = (const float*)d_in[13];
    const float* W_vm  = (const float*)d_in[14];
    const float* W_pn1 = (const float*)d_in[15];
    const float* b_pn1 = (const float*)d_in[16];
    const float* W_pn2 = (const float*)d_in[17];
    const float* b_pn2 = (const float*)d_in[18];
    const float* W_n1  = (const float*)d_in[19];
    const float* b_n1  = (const float*)d_in[20];
    const float* W_n2  = (const float*)d_in[21];
    const float* b_n2  = (const float*)d_in[22];
    const float* W_v1  = (const float*)d_in[23];
    const float* b_v1  = (const float*)d_in[24];
    const float* W_v2  = (const float*)d_in[25];
    float* out = (float*)d_out;

    int N = in_sizes[0] / 64;
    int P = in_sizes[3];

    size_t smA = (size_t)SMA_FLOATS * sizeof(float);  // 194240 B
    size_t smD = (size_t)SMD_FLOATS * sizeof(float);  // 135808 B
    cudaFuncSetAttribute(kA, cudaFuncAttributeMaxDynamicSharedMemorySize, (int)smA);
    cudaFuncSetAttribute(kD, cudaFuncAttributeMaxDynamicSharedMemorySize, (int)smD);

    kInit<<<(N * 128 + 255) / 256, 256>>>(N);
    kA<<<148, 512, smA>>>(h, x, idx_i, idx_j, W_ein, b_ein, W_eo1, b_eo1,
                          W_eo2, b_eo2, W_att, b_att, P);
    kB<<<(P + 255) / 256, 256>>>(idx_i, P);
    kC<<<608, 256>>>(idx_i, W_xm, P);
    kD<<<152, 256, smD>>>(h, x, v, W_pn1, b_pn1, W_pn2, b_pn2, W_n1, b_n1,
                          W_n2, b_n2, W_v1, b_v1, W_v2, W_vm, out, N);
}